// round 1
// baseline (speedup 1.0000x reference)
#include <cuda_runtime.h>
#include <cstdint>

// Problem shape (fixed by the dataset)
constexpr int Bc = 8, Hc = 16, Mc = 1024, Nc = 1024, Dc = 64;
constexpr int BHc = Bc * Hc;
constexpr long long OUT_ELEMS = (long long)BHc * Mc * Dc;   // 8,388,608
constexpr long long P_ELEMS   = (long long)BHc * Mc * Nc;   // 134,217,728

constexpr int MT = 32;        // M rows per CTA
constexpr int NTILE = 128;    // K/V rows staged per iteration
constexpr int THREADS = 256;
constexpr int KPAD = Dc + 1;  // 65: odd pad -> K column loads only 4-way conflicted

constexpr int Q_FLOATS = MT * Dc;        // 2048
constexpr int K_FLOATS = NTILE * KPAD;   // 8320
constexpr int S_FLOATS = MT * Nc;        // 32768
constexpr size_t SMEM_BYTES = (size_t)(Q_FLOATS + K_FLOATS + S_FLOATS) * 4 + (size_t)Nc * 4;

#define NEG_INF_F (-1e9f)

__global__ __launch_bounds__(THREADS, 1)
void attn_fused_kernel(const float* __restrict__ q,
                       const float* __restrict__ k,
                       const float* __restrict__ v,
                       const int*   __restrict__ mask,
                       float* __restrict__ outp,   // may be null
                       float* __restrict__ pp)     // may be null
{
    extern __shared__ float smem[];
    float* Qs = smem;                       // [MT][Dc]   natural
    float* Ks = Qs + Q_FLOATS;              // [NTILE][KPAD] (K tile, later V tile)
    float* S  = Ks + K_FLOATS;              // [MT][Nc]   scores -> probs
    int*   Msk = (int*)(S + S_FLOATS);      // [Nc]

    const int mtiles = Mc / MT;
    const int bh = blockIdx.x / mtiles;
    const int m0 = (blockIdx.x % mtiles) * MT;
    const int tid = threadIdx.x;

    const float scale = 1.0f / 32.0f;  // 1/sqrt(N=1024), faithful to the source bug

    // ---- load Q tile (coalesced float4) ----
    {
        const float4* qg = (const float4*)(q + (size_t)(bh * Mc + m0) * Dc);
        float4* Qs4 = (float4*)Qs;
        #pragma unroll
        for (int i = 0; i < Q_FLOATS / 4 / THREADS; i++)
            Qs4[i * THREADS + tid] = qg[i * THREADS + tid];
    }
    // ---- load mask row for this (b,h) ----
    for (int i = tid; i < Nc; i += THREADS)
        Msk[i] = mask[(size_t)bh * Nc + i];

    const int tr = tid >> 5;   // 0..7  (row group / warp id)
    const int tc = tid & 31;   // 0..31 (col group / lane)

    // =================== phase 1: S = Q K^T (raw, unscaled) ===================
    for (int nt = 0; nt < Nc / NTILE; nt++) {
        __syncthreads();  // previous tile's compute done before overwriting Ks
        // stage K tile [NTILE][Dc] -> Ks with row pad
        const float4* kg = (const float4*)(k + (size_t)(bh * Nc + nt * NTILE) * Dc);
        #pragma unroll
        for (int i = 0; i < (NTILE * Dc / 4) / THREADS; i++) {
            int f4 = i * THREADS + tid;
            float4 val = kg[f4];
            int row = f4 >> 4;         // 16 float4 per 64-float row
            int c   = (f4 & 15) * 4;
            float* dst = Ks + row * KPAD + c;
            dst[0] = val.x; dst[1] = val.y; dst[2] = val.z; dst[3] = val.w;
        }
        __syncthreads();

        float acc[4][4] = {};
        #pragma unroll 8
        for (int d = 0; d < Dc; d++) {
            float qv[4], kv[4];
            #pragma unroll
            for (int i = 0; i < 4; i++) qv[i] = Qs[(tr * 4 + i) * Dc + d];      // broadcast
            #pragma unroll
            for (int j = 0; j < 4; j++) kv[j] = Ks[(tc * 4 + j) * KPAD + d];    // ~4-way
            #pragma unroll
            for (int i = 0; i < 4; i++)
                #pragma unroll
                for (int j = 0; j < 4; j++)
                    acc[i][j] = fmaf(qv[i], kv[j], acc[i][j]);
        }
        #pragma unroll
        for (int i = 0; i < 4; i++) {
            float4 val = make_float4(acc[i][0], acc[i][1], acc[i][2], acc[i][3]);
            *(float4*)(S + (size_t)(tr * 4 + i) * Nc + nt * NTILE + tc * 4) = val;  // conflict-free
        }
    }
    __syncthreads();

    // =================== phase 2: masked softmax + p_attn write ===================
    // warp tr owns rows tr*4 .. tr*4+3 (the same rows it computed)
    #pragma unroll
    for (int rr = 0; rr < 4; rr++) {
        const int m = tr * 4 + rr;
        float* Srow = S + (size_t)m * Nc;
        float mx = NEG_INF_F;
        for (int n = tc; n < Nc; n += 32) {
            float vv = Msk[n] ? Srow[n] * scale : NEG_INF_F;
            Srow[n] = vv;
            mx = fmaxf(mx, vv);
        }
        #pragma unroll
        for (int o = 16; o; o >>= 1) mx = fmaxf(mx, __shfl_xor_sync(0xffffffffu, mx, o));
        float sum = 0.0f;
        for (int n = tc; n < Nc; n += 32) {
            float e = __expf(Srow[n] - mx);
            Srow[n] = e;
            sum += e;
        }
        #pragma unroll
        for (int o = 16; o; o >>= 1) sum += __shfl_xor_sync(0xffffffffu, sum, o);
        const float inv = 1.0f / sum;
        if (pp) {
            float* prow = pp + ((size_t)bh * Mc + m0 + m) * Nc;
            for (int n = tc; n < Nc; n += 32) {
                float pval = Srow[n] * inv;
                Srow[n] = pval;
                prow[n] = pval;   // coalesced
            }
        } else {
            for (int n = tc; n < Nc; n += 32) Srow[n] *= inv;
        }
    }

    // =================== phase 3: out = P V ===================
    // thread (tr,tc): rows tr*4..+3, dims tc*2, tc*2+1
    float oacc[4][2] = {};
    for (int nt = 0; nt < Nc / NTILE; nt++) {
        __syncthreads();  // also orders softmax S writes before PV S reads (nt==0)
        const float4* vg = (const float4*)(v + (size_t)(bh * Nc + nt * NTILE) * Dc);
        #pragma unroll
        for (int i = 0; i < (NTILE * Dc / 4) / THREADS; i++) {
            int f4 = i * THREADS + tid;
            float4 val = vg[f4];
            int row = f4 >> 4;
            int c   = (f4 & 15) * 4;
            float* dst = Ks + row * KPAD + c;   // reuse K staging buffer for V
            dst[0] = val.x; dst[1] = val.y; dst[2] = val.z; dst[3] = val.w;
        }
        __syncthreads();

        #pragma unroll 4
        for (int j = 0; j < NTILE; j++) {
            const int n = nt * NTILE + j;
            const float v0 = Ks[j * KPAD + tc * 2];
            const float v1 = Ks[j * KPAD + tc * 2 + 1];
            #pragma unroll
            for (int i = 0; i < 4; i++) {
                const float pval = S[(size_t)(tr * 4 + i) * Nc + n];  // broadcast
                oacc[i][0] = fmaf(pval, v0, oacc[i][0]);
                oacc[i][1] = fmaf(pval, v1, oacc[i][1]);
            }
        }
    }

    if (outp) {
        #pragma unroll
        for (int i = 0; i < 4; i++) {
            float2 val = make_float2(oacc[i][0], oacc[i][1]);
            *(float2*)(outp + ((size_t)bh * Mc + m0 + tr * 4 + i) * Dc + tc * 2) = val;
        }
    }
}

extern "C" void kernel_launch(void* const* d_in, const int* in_sizes, int n_in,
                              void* d_out, int out_size)
{
    const float* q    = (const float*)d_in[0];
    const float* k    = (const float*)d_in[1];
    const float* v    = (const float*)d_in[2];
    const int*   mask = (const int*)d_in[3];

    float* outp = nullptr;
    float* pp   = nullptr;
    long long osz = (long long)out_size;
    if (osz >= OUT_ELEMS + P_ELEMS) {            // (out, p_attn) concatenated
        outp = (float*)d_out;
        pp   = (float*)d_out + OUT_ELEMS;
    } else if (osz == P_ELEMS) {                 // only p_attn
        pp   = (float*)d_out;
    } else {                                     // only out
        outp = (float*)d_out;
    }

    cudaFuncSetAttribute(attn_fused_kernel,
                         cudaFuncAttributeMaxDynamicSharedMemorySize,
                         (int)SMEM_BYTES);

    dim3 grid(BHc * (Mc / MT));   // 4096 CTAs; consecutive CTAs share (b,h) -> K/V L2 reuse
    attn_fused_kernel<<<grid, THREADS, SMEM_BYTES>>>(q, k, v, mask, outp, pp);
}

// round 2
// speedup vs baseline: 1.2390x; 1.2390x over previous
#include <cuda_runtime.h>
#include <cstdint>

// Problem shape (fixed by the dataset)
constexpr int Bc = 8, Hc = 16, Mc = 1024, Nc = 1024, Dc = 64;
constexpr int BHc = Bc * Hc;
constexpr long long OUT_ELEMS = (long long)BHc * Mc * Dc;   // 8,388,608
constexpr long long P_ELEMS   = (long long)BHc * Mc * Nc;   // 134,217,728

constexpr int MT = 32;        // M rows per CTA
constexpr int NTILE = 128;    // K/V rows staged per iteration
constexpr int THREADS = 256;  // 8 warps

// SMEM pitches chosen for conflict-free mma fragment access:
constexpr int QP = 68;   // 68 % 32 == 4  -> A frag banks 4g+t distinct
constexpr int KP = 68;   // 68 % 32 == 4  -> B frag banks 4g+t distinct (QK^T)
constexpr int VP = 72;   // 72 % 32 == 8  -> B frag banks 8t+g distinct (PV)
constexpr int SP = 1028; // 1028 % 32 == 4 -> A frag (PV) distinct

constexpr int S_OFF   = 0;
constexpr int KV_OFF  = MT * SP;              // 32896 floats
constexpr int Q_OFF   = KV_OFF + NTILE * VP;  // + 9216
constexpr int MSK_OFF = Q_OFF + MT * QP;      // + 2176
constexpr int SMEM_FLOATS = MSK_OFF + Nc;     // + 1024 = 45312 floats
constexpr size_t SMEM_BYTES = (size_t)SMEM_FLOATS * 4;     // 181,248 B

#define NEG_INF_F (-1e9f)

__device__ __forceinline__ void tf32_split(float x, uint32_t& h, uint32_t& l) {
    asm("cvt.rna.tf32.f32 %0, %1;" : "=r"(h) : "f"(x));
    float hf = __uint_as_float(h);
    float r  = x - hf;
    asm("cvt.rna.tf32.f32 %0, %1;" : "=r"(l) : "f"(r));
}

__device__ __forceinline__ void mma_tf32(float* c, const uint32_t* a, uint32_t b0, uint32_t b1) {
    asm volatile(
        "mma.sync.aligned.m16n8k8.row.col.f32.tf32.tf32.f32 "
        "{%0,%1,%2,%3}, {%4,%5,%6,%7}, {%8,%9}, {%0,%1,%2,%3};\n"
        : "+f"(c[0]), "+f"(c[1]), "+f"(c[2]), "+f"(c[3])
        : "r"(a[0]), "r"(a[1]), "r"(a[2]), "r"(a[3]), "r"(b0), "r"(b1));
}

__global__ __launch_bounds__(THREADS, 1)
void attn_tc_kernel(const float* __restrict__ q,
                    const float* __restrict__ k,
                    const float* __restrict__ v,
                    const int*   __restrict__ mask,
                    float* __restrict__ outp,   // may be null
                    float* __restrict__ pp)     // may be null
{
    extern __shared__ float smem[];
    float* S  = smem + S_OFF;    // [MT][SP]   scores -> probs
    float* KV = smem + KV_OFF;   // K tile [NTILE][KP] / V tile [NTILE][VP]
    float* Qs = smem + Q_OFF;    // [MT][QP]
    int*  Msk = (int*)(smem + MSK_OFF);

    const int mtiles = Mc / MT;
    const int bh = blockIdx.x / mtiles;
    const int m0 = (blockIdx.x % mtiles) * MT;
    const int tid  = threadIdx.x;
    const int wid  = tid >> 5;
    const int lane = tid & 31;
    const int g = lane >> 2;   // groupID (0..7)
    const int t = lane & 3;    // threadID_in_group (0..3)

    const float scale = 1.0f / 32.0f;  // 1/sqrt(N=1024), faithful to the source bug

    // ---- load Q tile (coalesced float4 -> pitch QP) ----
    {
        const float4* qg = (const float4*)(q + (size_t)(bh * Mc + m0) * Dc);
        #pragma unroll
        for (int i = 0; i < (MT * Dc / 4) / THREADS; i++) {
            int f4 = i * THREADS + tid;
            float4 val = qg[f4];
            int row = f4 >> 4;          // 16 float4 per 64-float row
            int c   = (f4 & 15) * 4;
            float* dst = Qs + row * QP + c;
            dst[0] = val.x; dst[1] = val.y; dst[2] = val.z; dst[3] = val.w;
        }
    }
    for (int i = tid; i < Nc; i += THREADS)
        Msk[i] = mask[(size_t)bh * Nc + i];

    // =================== phase 1: S = Q K^T (tensor, 3xTF32) ===================
    for (int nt = 0; nt < Nc / NTILE; nt++) {
        __syncthreads();
        // stage K tile [NTILE][Dc] -> KV pitch KP
        const float4* kg = (const float4*)(k + (size_t)(bh * Nc + nt * NTILE) * Dc);
        #pragma unroll
        for (int i = 0; i < (NTILE * Dc / 4) / THREADS; i++) {
            int f4 = i * THREADS + tid;
            float4 val = kg[f4];
            int row = f4 >> 4;
            int c   = (f4 & 15) * 4;
            float* dst = KV + row * KP + c;
            dst[0] = val.x; dst[1] = val.y; dst[2] = val.z; dst[3] = val.w;
        }
        __syncthreads();

        // warp wid owns n-rows [wid*16, wid*16+16) of this tile -> 2 n-tiles of 8
        float acc[2][2][4] = {};   // [m-tile][n-tile][frag]
        #pragma unroll
        for (int kc = 0; kc < Dc / 8; kc++) {
            const int k0 = kc * 8;
            uint32_t ah[2][4], al[2][4];
            #pragma unroll
            for (int mi = 0; mi < 2; mi++) {
                const float* qb = Qs + (mi * 16 + g) * QP + k0;
                float a0 = qb[t];
                float a1 = qb[8 * QP + t];
                float a2 = qb[t + 4];
                float a3 = qb[8 * QP + t + 4];
                tf32_split(a0, ah[mi][0], al[mi][0]);
                tf32_split(a1, ah[mi][1], al[mi][1]);
                tf32_split(a2, ah[mi][2], al[mi][2]);
                tf32_split(a3, ah[mi][3], al[mi][3]);
            }
            #pragma unroll
            for (int ni = 0; ni < 2; ni++) {
                const int nb = wid * 16 + ni * 8;
                float b0f = KV[(nb + g) * KP + k0 + t];
                float b1f = KV[(nb + g) * KP + k0 + t + 4];
                uint32_t bh0, bl0, bh1, bl1;
                tf32_split(b0f, bh0, bl0);
                tf32_split(b1f, bh1, bl1);
                #pragma unroll
                for (int mi = 0; mi < 2; mi++) {
                    mma_tf32(acc[mi][ni], ah[mi], bh0, bh1);  // hi*hi
                    mma_tf32(acc[mi][ni], al[mi], bh0, bh1);  // lo*hi
                    mma_tf32(acc[mi][ni], ah[mi], bl0, bl1);  // hi*lo
                }
            }
        }
        // write acc -> S  (c0:(g,2t) c1:(g,2t+1) c2:(g+8,2t) c3:(g+8,2t+1))
        #pragma unroll
        for (int mi = 0; mi < 2; mi++) {
            #pragma unroll
            for (int ni = 0; ni < 2; ni++) {
                const int m = mi * 16 + g;
                const int n = nt * NTILE + wid * 16 + ni * 8 + 2 * t;
                *(float2*)(S + (size_t)m * SP + n) =
                    make_float2(acc[mi][ni][0], acc[mi][ni][1]);
                *(float2*)(S + (size_t)(m + 8) * SP + n) =
                    make_float2(acc[mi][ni][2], acc[mi][ni][3]);
            }
        }
    }
    __syncthreads();

    // =================== phase 2: masked softmax + p_attn write ===================
    #pragma unroll
    for (int rr = 0; rr < 4; rr++) {
        const int m = wid * 4 + rr;
        float* Srow = S + (size_t)m * SP;
        float mx = NEG_INF_F;
        for (int n = lane; n < Nc; n += 32) {
            float vv = Msk[n] ? Srow[n] * scale : NEG_INF_F;
            Srow[n] = vv;
            mx = fmaxf(mx, vv);
        }
        #pragma unroll
        for (int o = 16; o; o >>= 1) mx = fmaxf(mx, __shfl_xor_sync(0xffffffffu, mx, o));
        float sum = 0.0f;
        for (int n = lane; n < Nc; n += 32) {
            float e = __expf(Srow[n] - mx);
            Srow[n] = e;
            sum += e;
        }
        #pragma unroll
        for (int o = 16; o; o >>= 1) sum += __shfl_xor_sync(0xffffffffu, sum, o);
        const float inv = 1.0f / sum;
        if (pp) {
            float* prow = pp + ((size_t)bh * Mc + m0 + m) * Nc;
            for (int n = lane; n < Nc; n += 32) {
                float pval = Srow[n] * inv;
                Srow[n] = pval;
                prow[n] = pval;
            }
        } else {
            for (int n = lane; n < Nc; n += 32) Srow[n] *= inv;
        }
    }

    // =================== phase 3: out = P V (tensor, 3xTF32) ===================
    // warp wid owns d-columns [wid*8, wid*8+8)
    const int d0 = wid * 8;
    float oacc[2][4] = {};
    for (int nt = 0; nt < Nc / NTILE; nt++) {
        __syncthreads();
        // stage V tile [NTILE][Dc] -> KV pitch VP
        const float4* vg = (const float4*)(v + (size_t)(bh * Nc + nt * NTILE) * Dc);
        #pragma unroll
        for (int i = 0; i < (NTILE * Dc / 4) / THREADS; i++) {
            int f4 = i * THREADS + tid;
            float4 val = vg[f4];
            int row = f4 >> 4;
            int c   = (f4 & 15) * 4;
            float* dst = KV + row * VP + c;
            dst[0] = val.x; dst[1] = val.y; dst[2] = val.z; dst[3] = val.w;
        }
        __syncthreads();

        #pragma unroll
        for (int kc = 0; kc < NTILE / 8; kc++) {
            const int kk = kc * 8;
            uint32_t ah[2][4], al[2][4];
            #pragma unroll
            for (int mi = 0; mi < 2; mi++) {
                const float* sb = S + (size_t)(mi * 16 + g) * SP + nt * NTILE + kk;
                float a0 = sb[t];
                float a1 = sb[8 * SP + t];
                float a2 = sb[t + 4];
                float a3 = sb[8 * SP + t + 4];
                tf32_split(a0, ah[mi][0], al[mi][0]);
                tf32_split(a1, ah[mi][1], al[mi][1]);
                tf32_split(a2, ah[mi][2], al[mi][2]);
                tf32_split(a3, ah[mi][3], al[mi][3]);
            }
            float b0f = KV[(kk + t) * VP + d0 + g];
            float b1f = KV[(kk + t + 4) * VP + d0 + g];
            uint32_t bh0, bl0, bh1, bl1;
            tf32_split(b0f, bh0, bl0);
            tf32_split(b1f, bh1, bl1);
            #pragma unroll
            for (int mi = 0; mi < 2; mi++) {
                mma_tf32(oacc[mi], ah[mi], bh0, bh1);
                mma_tf32(oacc[mi], al[mi], bh0, bh1);
                mma_tf32(oacc[mi], ah[mi], bl0, bl1);
            }
        }
    }

    if (outp) {
        #pragma unroll
        for (int mi = 0; mi < 2; mi++) {
            const int m = mi * 16 + g;
            float* ob = outp + ((size_t)bh * Mc + m0 + m) * Dc + d0 + 2 * t;
            *(float2*)ob = make_float2(oacc[mi][0], oacc[mi][1]);
            *(float2*)(ob + 8 * Dc) = make_float2(oacc[mi][2], oacc[mi][3]);
        }
    }
}

extern "C" void kernel_launch(void* const* d_in, const int* in_sizes, int n_in,
                              void* d_out, int out_size)
{
    const float* q    = (const float*)d_in[0];
    const float* k    = (const float*)d_in[1];
    const float* v    = (const float*)d_in[2];
    const int*   mask = (const int*)d_in[3];

    float* outp = nullptr;
    float* pp   = nullptr;
    long long osz = (long long)out_size;
    if (osz >= OUT_ELEMS + P_ELEMS) {            // (out, p_attn) concatenated
        outp = (float*)d_out;
        pp   = (float*)d_out + OUT_ELEMS;
    } else if (osz == P_ELEMS) {                 // only p_attn
        pp   = (float*)d_out;
    } else {                                     // only out
        outp = (float*)d_out;
    }

    cudaFuncSetAttribute(attn_tc_kernel,
                         cudaFuncAttributeMaxDynamicSharedMemorySize,
                         (int)SMEM_BYTES);

    dim3 grid(BHc * (Mc / MT));   // 4096 CTAs; consecutive CTAs share (b,h) -> K/V L2 reuse
    attn_tc_kernel<<<grid, THREADS, SMEM_BYTES>>>(q, k, v, mask, outp, pp);
}

// round 3
// speedup vs baseline: 1.3377x; 1.0797x over previous
#include <cuda_runtime.h>
#include <cstdint>

// Problem shape (fixed by the dataset)
constexpr int Bc = 8, Hc = 16, Mc = 1024, Nc = 1024, Dc = 64;
constexpr int BHc = Bc * Hc;
constexpr long long OUT_ELEMS = (long long)BHc * Mc * Dc;   // 8,388,608
constexpr long long P_ELEMS   = (long long)BHc * Mc * Nc;   // 134,217,728

constexpr int MT = 32;        // M rows per CTA
constexpr int NTILE = 128;    // K/V rows staged per iteration
constexpr int THREADS = 512;  // 16 warps

// SMEM pitches for conflict-free mma fragment access:
//  pattern "row g(0..7), col t(0..3)+{0,4}" needs pitch % 32 == 4 -> banks 4g+t distinct
//  pattern "row t(0..3)+{0,4}, col g(0..7)" needs pitch % 32 == 8 -> banks 8t+g distinct
constexpr int QP = 68;   // Q   (A-frag of QK^T)
constexpr int KP = 68;   // K   (B-frag of QK^T)
constexpr int VP = 72;   // V   (B-frag of PV)
constexpr int SP = 1028; // S   (A-frag of PV; 1028 % 32 == 4)

constexpr int KVBUF = NTILE * VP;  // 9216 floats: holds K (pitch 68) or V (pitch 72)

constexpr int S_OFF   = 0;
constexpr int KH_OFF  = S_OFF  + MT * SP;      // 32896
constexpr int KL_OFF  = KH_OFF + KVBUF;        // 42112
constexpr int QH_OFF  = KL_OFF + KVBUF;        // 51328
constexpr int QL_OFF  = QH_OFF + MT * QP;      // 53504
constexpr int MSK_OFF = QL_OFF + MT * QP;      // 55680
constexpr int SMEM_FLOATS = MSK_OFF + Nc;      // 56704
constexpr size_t SMEM_BYTES = (size_t)SMEM_FLOATS * 4;   // 226,816 B

#define NEG_INF_F (-1e9f)

__device__ __forceinline__ void tf32_split(float x, uint32_t& h, uint32_t& l) {
    asm("cvt.rna.tf32.f32 %0, %1;" : "=r"(h) : "f"(x));
    float hf = __uint_as_float(h);
    float r  = x - hf;
    asm("cvt.rna.tf32.f32 %0, %1;" : "=r"(l) : "f"(r));
}

__device__ __forceinline__ void mma_tf32(float* c, const uint32_t* a, uint32_t b0, uint32_t b1) {
    asm volatile(
        "mma.sync.aligned.m16n8k8.row.col.f32.tf32.tf32.f32 "
        "{%0,%1,%2,%3}, {%4,%5,%6,%7}, {%8,%9}, {%0,%1,%2,%3};\n"
        : "+f"(c[0]), "+f"(c[1]), "+f"(c[2]), "+f"(c[3])
        : "r"(a[0]), "r"(a[1]), "r"(a[2]), "r"(a[3]), "r"(b0), "r"(b1));
}

__global__ __launch_bounds__(THREADS, 1)
void attn_tc_kernel(const float* __restrict__ q,
                    const float* __restrict__ k,
                    const float* __restrict__ v,
                    const int*   __restrict__ mask,
                    float* __restrict__ outp,   // may be null
                    float* __restrict__ pp)     // may be null
{
    extern __shared__ float smem[];
    float*    S  = smem + S_OFF;            // [MT][SP]  scores -> probs (fp32)
    uint32_t* KH = (uint32_t*)(smem + KH_OFF);  // K/V tile tf32-hi
    uint32_t* KL = (uint32_t*)(smem + KL_OFF);  // K/V tile tf32-lo
    uint32_t* QH = (uint32_t*)(smem + QH_OFF);  // [MT][QP] Q tf32-hi
    uint32_t* QL = (uint32_t*)(smem + QL_OFF);  // [MT][QP] Q tf32-lo
    int*     Msk = (int*)(smem + MSK_OFF);

    const int mtiles = Mc / MT;
    const int bh = blockIdx.x / mtiles;
    const int m0 = (blockIdx.x % mtiles) * MT;
    const int tid  = threadIdx.x;
    const int wid  = tid >> 5;       // 0..15
    const int lane = tid & 31;
    const int g = lane >> 2;         // 0..7
    const int t = lane & 3;          // 0..3

    const float scale = 1.0f / 32.0f;  // 1/sqrt(N=1024), faithful to the source bug

    // ---- load + pre-split Q tile ----
    {
        const float4* qg = (const float4*)(q + (size_t)(bh * Mc + m0) * Dc);
        int f4 = tid;                       // 512 float4 total, 512 threads -> 1 each
        float4 val = qg[f4];
        int row = f4 >> 4;
        int c   = (f4 & 15) * 4;
        uint32_t* dh = QH + row * QP + c;
        uint32_t* dl = QL + row * QP + c;
        tf32_split(val.x, dh[0], dl[0]);
        tf32_split(val.y, dh[1], dl[1]);
        tf32_split(val.z, dh[2], dl[2]);
        tf32_split(val.w, dh[3], dl[3]);
    }
    #pragma unroll
    for (int i = 0; i < Nc / THREADS; i++)
        Msk[i * THREADS + tid] = mask[(size_t)bh * Nc + i * THREADS + tid];

    // =================== phase 1: S = Q K^T (tensor, 3xTF32) ===================
    // warp wid owns n-rows [wid*8, wid*8+8) of the staged tile
    for (int nt = 0; nt < Nc / NTILE; nt++) {
        __syncthreads();
        // stage + split K tile [NTILE][Dc] -> KH/KL pitch KP
        const float4* kg = (const float4*)(k + (size_t)(bh * Nc + nt * NTILE) * Dc);
        #pragma unroll
        for (int i = 0; i < (NTILE * Dc / 4) / THREADS; i++) {
            int f4 = i * THREADS + tid;
            float4 val = kg[f4];
            int row = f4 >> 4;
            int c   = (f4 & 15) * 4;
            uint32_t* dh = KH + row * KP + c;
            uint32_t* dl = KL + row * KP + c;
            tf32_split(val.x, dh[0], dl[0]);
            tf32_split(val.y, dh[1], dl[1]);
            tf32_split(val.z, dh[2], dl[2]);
            tf32_split(val.w, dh[3], dl[3]);
        }
        __syncthreads();

        float acc[2][4] = {};   // [m-tile][frag]
        const int nb = wid * 8;
        #pragma unroll
        for (int kc = 0; kc < Dc / 8; kc++) {
            const int k0 = kc * 8;
            uint32_t ah[2][4], al[2][4];
            #pragma unroll
            for (int mi = 0; mi < 2; mi++) {
                const int base = (mi * 16 + g) * QP + k0;
                ah[mi][0] = QH[base + t];            al[mi][0] = QL[base + t];
                ah[mi][1] = QH[base + 8 * QP + t];   al[mi][1] = QL[base + 8 * QP + t];
                ah[mi][2] = QH[base + t + 4];        al[mi][2] = QL[base + t + 4];
                ah[mi][3] = QH[base + 8 * QP + t + 4]; al[mi][3] = QL[base + 8 * QP + t + 4];
            }
            const int bbase = (nb + g) * KP + k0;
            uint32_t bh0 = KH[bbase + t], bh1 = KH[bbase + t + 4];
            uint32_t bl0 = KL[bbase + t], bl1 = KL[bbase + t + 4];
            #pragma unroll
            for (int mi = 0; mi < 2; mi++) {
                mma_tf32(acc[mi], ah[mi], bh0, bh1);  // hi*hi
                mma_tf32(acc[mi], al[mi], bh0, bh1);  // lo*hi
                mma_tf32(acc[mi], ah[mi], bl0, bl1);  // hi*lo
            }
        }
        // store acc -> S  (c0:(g,2t) c1:(g,2t+1) c2:(g+8,2t) c3:(g+8,2t+1))
        #pragma unroll
        for (int mi = 0; mi < 2; mi++) {
            const int m = mi * 16 + g;
            const int n = nt * NTILE + nb + 2 * t;
            *(float2*)(S + (size_t)m * SP + n)       = make_float2(acc[mi][0], acc[mi][1]);
            *(float2*)(S + (size_t)(m + 8) * SP + n) = make_float2(acc[mi][2], acc[mi][3]);
        }
    }
    __syncthreads();

    // =================== phase 2: masked softmax + p_attn write ===================
    // warp wid owns rows 2*wid, 2*wid+1
    #pragma unroll
    for (int rr = 0; rr < 2; rr++) {
        const int m = wid * 2 + rr;
        float* Srow = S + (size_t)m * SP;
        float mx = NEG_INF_F;
        #pragma unroll 4
        for (int n = lane; n < Nc; n += 32) {
            float vv = Msk[n] ? Srow[n] * scale : NEG_INF_F;
            Srow[n] = vv;
            mx = fmaxf(mx, vv);
        }
        #pragma unroll
        for (int o = 16; o; o >>= 1) mx = fmaxf(mx, __shfl_xor_sync(0xffffffffu, mx, o));
        float sum = 0.0f;
        #pragma unroll 4
        for (int n = lane; n < Nc; n += 32) {
            float e = __expf(Srow[n] - mx);
            Srow[n] = e;
            sum += e;
        }
        #pragma unroll
        for (int o = 16; o; o >>= 1) sum += __shfl_xor_sync(0xffffffffu, sum, o);
        const float inv = 1.0f / sum;
        if (pp) {
            float* prow = pp + ((size_t)bh * Mc + m0 + m) * Nc;
            #pragma unroll 4
            for (int n = lane; n < Nc; n += 32) {
                float pval = Srow[n] * inv;
                Srow[n] = pval;
                prow[n] = pval;   // coalesced
            }
        } else {
            #pragma unroll 4
            for (int n = lane; n < Nc; n += 32) Srow[n] *= inv;
        }
    }

    // =================== phase 3: out = P V (tensor, 3xTF32) ===================
    // warp wid: m-half = wid>>3 (16 rows), d-slice = (wid&7)*8
    const int mi = wid >> 3;
    const int d0 = (wid & 7) * 8;
    float oacc[4] = {};
    for (int nt = 0; nt < Nc / NTILE; nt++) {
        __syncthreads();   // (nt==0: also orders softmax S writes before PV reads)
        // stage + split V tile [NTILE][Dc] -> KH/KL pitch VP (reuse K buffers)
        const float4* vg = (const float4*)(v + (size_t)(bh * Nc + nt * NTILE) * Dc);
        #pragma unroll
        for (int i = 0; i < (NTILE * Dc / 4) / THREADS; i++) {
            int f4 = i * THREADS + tid;
            float4 val = vg[f4];
            int row = f4 >> 4;
            int c   = (f4 & 15) * 4;
            uint32_t* dh = KH + row * VP + c;
            uint32_t* dl = KL + row * VP + c;
            tf32_split(val.x, dh[0], dl[0]);
            tf32_split(val.y, dh[1], dl[1]);
            tf32_split(val.z, dh[2], dl[2]);
            tf32_split(val.w, dh[3], dl[3]);
        }
        __syncthreads();

        #pragma unroll
        for (int kc = 0; kc < NTILE / 8; kc++) {
            const int kk = kc * 8;
            const float* sb = S + (size_t)(mi * 16 + g) * SP + nt * NTILE + kk;
            uint32_t ah[4], al[4];
            tf32_split(sb[t],              ah[0], al[0]);
            tf32_split(sb[8 * SP + t],     ah[1], al[1]);
            tf32_split(sb[t + 4],          ah[2], al[2]);
            tf32_split(sb[8 * SP + t + 4], ah[3], al[3]);
            const int b0i = (kk + t) * VP + d0 + g;
            const int b1i = (kk + t + 4) * VP + d0 + g;
            uint32_t bh0 = KH[b0i], bh1 = KH[b1i];
            uint32_t bl0 = KL[b0i], bl1 = KL[b1i];
            mma_tf32(oacc, ah, bh0, bh1);
            mma_tf32(oacc, al, bh0, bh1);
            mma_tf32(oacc, ah, bl0, bl1);
        }
    }

    if (outp) {
        const int m = mi * 16 + g;
        float* ob = outp + ((size_t)bh * Mc + m0 + m) * Dc + d0 + 2 * t;
        *(float2*)ob            = make_float2(oacc[0], oacc[1]);
        *(float2*)(ob + 8 * Dc) = make_float2(oacc[2], oacc[3]);
    }
}

extern "C" void kernel_launch(void* const* d_in, const int* in_sizes, int n_in,
                              void* d_out, int out_size)
{
    const float* q    = (const float*)d_in[0];
    const float* k    = (const float*)d_in[1];
    const float* v    = (const float*)d_in[2];
    const int*   mask = (const int*)d_in[3];

    float* outp = nullptr;
    float* pp   = nullptr;
    long long osz = (long long)out_size;
    if (osz >= OUT_ELEMS + P_ELEMS) {            // (out, p_attn) concatenated
        outp = (float*)d_out;
        pp   = (float*)d_out + OUT_ELEMS;
    } else if (osz == P_ELEMS) {                 // only p_attn
        pp   = (float*)d_out;
    } else {                                     // only out
        outp = (float*)d_out;
    }

    cudaFuncSetAttribute(attn_tc_kernel,
                         cudaFuncAttributeMaxDynamicSharedMemorySize,
                         (int)SMEM_BYTES);

    dim3 grid(BHc * (Mc / MT));   // 4096 CTAs; consecutive CTAs share (b,h) -> K/V L2 reuse
    attn_tc_kernel<<<grid, THREADS, SMEM_BYTES>>>(q, k, v, mask, outp, pp);
}

// round 4
// speedup vs baseline: 1.4718x; 1.1002x over previous
#include <cuda_runtime.h>
#include <cstdint>

// Problem shape (fixed by the dataset)
constexpr int Bc = 8, Hc = 16, Mc = 1024, Nc = 1024, Dc = 64;
constexpr int BHc = Bc * Hc;
constexpr long long OUT_ELEMS = (long long)BHc * Mc * Dc;   // 8,388,608
constexpr long long P_ELEMS   = (long long)BHc * Mc * Nc;   // 134,217,728

constexpr int MT = 32;        // M rows per CTA
constexpr int NTILE = 128;    // K/V rows staged per iteration
constexpr int THREADS = 512;  // 16 warps

// smem pitches (floats), chosen for conflict-free fragment access:
//  pattern "(row g)*pitch + t"  needs pitch%32==4  -> banks 4g+t distinct
//  pattern "(row t)*pitch + g"  needs pitch%32==8  -> banks 8t+g distinct
constexpr int KP = 68;    // raw K tile
constexpr int VP = 72;    // raw V tile
constexpr int SP = 1028;  // S (scores/probs)

constexpr int S_OFF   = 0;                       // 32*1028 = 32896 floats
constexpr int KV_OFF  = S_OFF + MT * SP;         // 9216 floats (max of K/V pitch)
constexpr int RED_OFF = KV_OFF + NTILE * VP;     // 4096 floats (k-split reduce)
constexpr int MSK_OFF = RED_OFF + 4096;          // 1024 ints
constexpr int SMEM_FLOATS = MSK_OFF + Nc;        // 47232
constexpr size_t SMEM_BYTES = (size_t)SMEM_FLOATS * 4;   // 188,928 B

#define NEG_INF_F (-1e9f)

__device__ __forceinline__ void tf32_split(float x, uint32_t& h, uint32_t& l) {
    asm("cvt.rna.tf32.f32 %0, %1;" : "=r"(h) : "f"(x));
    float hf = __uint_as_float(h);
    float r  = x - hf;
    asm("cvt.rna.tf32.f32 %0, %1;" : "=r"(l) : "f"(r));
}

__device__ __forceinline__ void mma_tf32(float* c, const uint32_t* a, uint32_t b0, uint32_t b1) {
    asm volatile(
        "mma.sync.aligned.m16n8k8.row.col.f32.tf32.tf32.f32 "
        "{%0,%1,%2,%3}, {%4,%5,%6,%7}, {%8,%9}, {%0,%1,%2,%3};\n"
        : "+f"(c[0]), "+f"(c[1]), "+f"(c[2]), "+f"(c[3])
        : "r"(a[0]), "r"(a[1]), "r"(a[2]), "r"(a[3]), "r"(b0), "r"(b1));
}

__global__ __launch_bounds__(THREADS, 1)
void attn_tc_kernel(const float* __restrict__ q,
                    const float* __restrict__ k,
                    const float* __restrict__ v,
                    const int*   __restrict__ mask,
                    float* __restrict__ outp,   // may be null
                    float* __restrict__ pp)     // may be null
{
    extern __shared__ float smem[];
    float* S    = smem + S_OFF;    // [MT][SP]  scores -> probs
    float* KV   = smem + KV_OFF;   // raw K tile [NTILE][KP] / raw V tile [NTILE][VP]
    float* Red  = smem + RED_OFF;  // cross-warp k-split partial sums
    int*   Msk  = (int*)(smem + MSK_OFF);

    const int mtiles = Mc / MT;
    const int bh = blockIdx.x / mtiles;
    const int m0 = (blockIdx.x % mtiles) * MT;
    const int tid  = threadIdx.x;
    const int wid  = tid >> 5;       // 0..15
    const int lane = tid & 31;
    const int g = lane >> 2;         // 0..7
    const int t = lane & 3;          // 0..3

    const float scale = 1.0f / 32.0f;  // 1/sqrt(N=1024), faithful to the source bug

    // ---- mask ----
    #pragma unroll
    for (int i = 0; i < Nc / THREADS; i++)
        Msk[i * THREADS + tid] = mask[(size_t)bh * Nc + i * THREADS + tid];

    // =================== phase 1: S = Q K^T (tensor, 3xTF32, k-split) ==========
    // warp = (kh, nbp): kh = k-half (k [kh*32, kh*32+32)), nbp -> n [nbp*16, +16)
    const int kh  = wid >> 3;
    const int nbp = wid & 7;
    const int nb0 = nbp * 16;

    // hoist A (Q) fragments in registers for the warp's k-half: gather from gmem
    uint32_t ah[2][4][4], al[2][4][4];   // [mi][kc-local][frag]
    {
        const float* qb = q + (size_t)(bh * Mc + m0) * Dc;
        #pragma unroll
        for (int mi = 0; mi < 2; mi++)
            #pragma unroll
            for (int kc = 0; kc < 4; kc++)
                #pragma unroll
                for (int ri = 0; ri < 4; ri++) {
                    int row = mi * 16 + g + (ri & 1) * 8;
                    int col = (kh * 4 + kc) * 8 + t + (ri >> 1) * 4;
                    tf32_split(__ldg(qb + row * Dc + col), ah[mi][kc][ri], al[mi][kc][ri]);
                }
    }

    for (int nt = 0; nt < Nc / NTILE; nt++) {
        __syncthreads();
        // stage raw K tile [NTILE][Dc] -> pitch KP (float4 STS, 16B aligned)
        {
            const float4* kg = (const float4*)(k + (size_t)(bh * Nc + nt * NTILE) * Dc);
            #pragma unroll
            for (int i = 0; i < (NTILE * Dc / 4) / THREADS; i++) {
                int f4 = i * THREADS + tid;
                float4 val = kg[f4];
                int row = f4 >> 4;
                int c   = (f4 & 15) * 4;
                *(float4*)(KV + row * KP + c) = val;
            }
        }
        __syncthreads();

        float acc[2][2][4] = {};   // [nblk][mi][frag]
        #pragma unroll
        for (int kc = 0; kc < 4; kc++) {
            const int k0 = (kh * 4 + kc) * 8;
            #pragma unroll
            for (int nb = 0; nb < 2; nb++) {
                const int base = (nb0 + nb * 8 + g) * KP + k0;
                uint32_t bh0, bl0, bh1, bl1;
                tf32_split(KV[base + t],     bh0, bl0);
                tf32_split(KV[base + t + 4], bh1, bl1);
                #pragma unroll
                for (int mi = 0; mi < 2; mi++) {
                    mma_tf32(acc[nb][mi], ah[mi][kc], bh0, bh1);  // hi*hi
                    mma_tf32(acc[nb][mi], al[mi][kc], bh0, bh1);  // lo*hi
                    mma_tf32(acc[nb][mi], ah[mi][kc], bl0, bl1);  // hi*lo
                }
            }
        }
        // k-split reduce: kh=1 publishes, kh=0 adds and stores S
        if (kh == 1) {
            #pragma unroll
            for (int nb = 0; nb < 2; nb++)
                #pragma unroll
                for (int mi = 0; mi < 2; mi++)
                    *(float4*)(Red + (((nbp * 2 + nb) * 2 + mi) * 32 + lane) * 4) =
                        make_float4(acc[nb][mi][0], acc[nb][mi][1], acc[nb][mi][2], acc[nb][mi][3]);
        }
        __syncthreads();
        if (kh == 0) {
            #pragma unroll
            for (int nb = 0; nb < 2; nb++)
                #pragma unroll
                for (int mi = 0; mi < 2; mi++) {
                    float4 r = *(float4*)(Red + (((nbp * 2 + nb) * 2 + mi) * 32 + lane) * 4);
                    const int m = mi * 16 + g;
                    const int n = nt * NTILE + nb0 + nb * 8 + 2 * t;
                    *(float2*)(S + (size_t)m * SP + n) =
                        make_float2(acc[nb][mi][0] + r.x, acc[nb][mi][1] + r.y);
                    *(float2*)(S + (size_t)(m + 8) * SP + n) =
                        make_float2(acc[nb][mi][2] + r.z, acc[nb][mi][3] + r.w);
                }
        }
    }
    __syncthreads();

    // =================== phase 2: register-resident masked softmax =============
    // warp wid owns rows 2*wid, 2*wid+1; row held in 32 regs
    #pragma unroll
    for (int rr = 0; rr < 2; rr++) {
        const int m = wid * 2 + rr;
        float* Srow = S + (size_t)m * SP;
        float r[32];
        #pragma unroll
        for (int i = 0; i < 32; i++) {
            float vv = Srow[i * 32 + lane];
            r[i] = Msk[i * 32 + lane] ? vv * scale : NEG_INF_F;
        }
        float mx = r[0];
        #pragma unroll
        for (int i = 1; i < 32; i++) mx = fmaxf(mx, r[i]);
        #pragma unroll
        for (int o = 16; o; o >>= 1) mx = fmaxf(mx, __shfl_xor_sync(0xffffffffu, mx, o));
        float sum = 0.0f;
        #pragma unroll
        for (int i = 0; i < 32; i++) { r[i] = __expf(r[i] - mx); sum += r[i]; }
        #pragma unroll
        for (int o = 16; o; o >>= 1) sum += __shfl_xor_sync(0xffffffffu, sum, o);
        const float inv = 1.0f / sum;
        if (pp) {
            float* prow = pp + ((size_t)bh * Mc + m0 + m) * Nc;
            #pragma unroll
            for (int i = 0; i < 32; i++) {
                float pval = r[i] * inv;
                Srow[i * 32 + lane] = pval;
                prow[i * 32 + lane] = pval;   // coalesced
            }
        } else {
            #pragma unroll
            for (int i = 0; i < 32; i++) Srow[i * 32 + lane] = r[i] * inv;
        }
    }

    // =================== phase 3: out = P V (tensor, 3xTF32, k-split) ==========
    // warp = (kh3, dp, mi3): mi3 = m-half, dp -> d [dp*16,+16), kh3 = kc-half per tile
    const int mi3 = wid & 1;
    const int dp  = (wid >> 1) & 3;
    const int kh3 = wid >> 3;
    const int d0  = dp * 16;

    float oacc[2][4] = {};   // [dblk][frag]
    for (int nt = 0; nt < Nc / NTILE; nt++) {
        __syncthreads();   // prior tile reads done (nt==0: softmax S writes done)
        // stage raw V tile [NTILE][Dc] -> pitch VP
        {
            const float4* vg = (const float4*)(v + (size_t)(bh * Nc + nt * NTILE) * Dc);
            #pragma unroll
            for (int i = 0; i < (NTILE * Dc / 4) / THREADS; i++) {
                int f4 = i * THREADS + tid;
                float4 val = vg[f4];
                int row = f4 >> 4;
                int c   = (f4 & 15) * 4;
                *(float4*)(KV + row * VP + c) = val;
            }
        }
        __syncthreads();

        #pragma unroll
        for (int kc = 0; kc < 8; kc++) {
            const int kk = (kh3 * 8 + kc) * 8;
            // A fragment from S (probs), split in-loop
            const float* sb = S + (size_t)(mi3 * 16 + g) * SP + nt * NTILE + kk;
            uint32_t pah[4], pal[4];
            tf32_split(sb[t],              pah[0], pal[0]);
            tf32_split(sb[8 * SP + t],     pah[1], pal[1]);
            tf32_split(sb[t + 4],          pah[2], pal[2]);
            tf32_split(sb[8 * SP + t + 4], pah[3], pal[3]);
            #pragma unroll
            for (int db = 0; db < 2; db++) {
                const int base = (kk + t) * VP + d0 + db * 8 + g;
                uint32_t bh0, bl0, bh1, bl1;
                tf32_split(KV[base],          bh0, bl0);
                tf32_split(KV[base + 4 * VP], bh1, bl1);
                mma_tf32(oacc[db], pah, bh0, bh1);
                mma_tf32(oacc[db], pal, bh0, bh1);
                mma_tf32(oacc[db], pah, bl0, bl1);
            }
        }
    }
    __syncthreads();
    // k-split reduce of output partials
    if (kh3 == 1) {
        #pragma unroll
        for (int db = 0; db < 2; db++)
            *(float4*)(Red + (((wid & 7) * 2 + db) * 32 + lane) * 4) =
                make_float4(oacc[db][0], oacc[db][1], oacc[db][2], oacc[db][3]);
    }
    __syncthreads();
    if (kh3 == 0 && outp) {
        #pragma unroll
        for (int db = 0; db < 2; db++) {
            float4 r = *(float4*)(Red + (((wid & 7) * 2 + db) * 32 + lane) * 4);
            const int m = mi3 * 16 + g;
            float* ob = outp + ((size_t)bh * Mc + m0 + m) * Dc + d0 + db * 8 + 2 * t;
            *(float2*)ob            = make_float2(oacc[db][0] + r.x, oacc[db][1] + r.y);
            *(float2*)(ob + 8 * Dc) = make_float2(oacc[db][2] + r.z, oacc[db][3] + r.w);
        }
    }
}

extern "C" void kernel_launch(void* const* d_in, const int* in_sizes, int n_in,
                              void* d_out, int out_size)
{
    const float* q    = (const float*)d_in[0];
    const float* k    = (const float*)d_in[1];
    const float* v    = (const float*)d_in[2];
    const int*   mask = (const int*)d_in[3];

    float* outp = nullptr;
    float* pp   = nullptr;
    long long osz = (long long)out_size;
    if (osz >= OUT_ELEMS + P_ELEMS) {            // (out, p_attn) concatenated
        outp = (float*)d_out;
        pp   = (float*)d_out + OUT_ELEMS;
    } else if (osz == P_ELEMS) {                 // only p_attn
        pp   = (float*)d_out;
    } else {                                     // only out
        outp = (float*)d_out;
    }

    cudaFuncSetAttribute(attn_tc_kernel,
                         cudaFuncAttributeMaxDynamicSharedMemorySize,
                         (int)SMEM_BYTES);

    dim3 grid(BHc * (Mc / MT));   // 4096 CTAs; consecutive CTAs share (b,h) -> K/V L2 reuse
    attn_tc_kernel<<<grid, THREADS, SMEM_BYTES>>>(q, k, v, mask, outp, pp);
}

// round 5
// speedup vs baseline: 1.9868x; 1.3499x over previous
#include <cuda_runtime.h>
#include <cstdint>

// Problem shape (fixed by the dataset)
constexpr int Bc = 8, Hc = 16, Mc = 1024, Nc = 1024, Dc = 64;
constexpr int BHc = Bc * Hc;
constexpr long long OUT_ELEMS = (long long)BHc * Mc * Dc;   // 8,388,608
constexpr long long P_ELEMS   = (long long)BHc * Mc * Nc;   // 134,217,728

constexpr int MT = 32;        // M rows per CTA
constexpr int NTILE = 128;    // K/V rows staged per iteration
constexpr int THREADS = 256;  // 8 warps -> 3 CTAs/SM

// smem pitches (floats) for conflict-free fragment access:
//  "(row g)*pitch + t" pattern needs pitch%32==4  (banks 4g+t distinct)
//  "(row t)*pitch + g" pattern needs pitch%32==8  (banks 8t+g distinct)
constexpr int QP = 68;
constexpr int KP = 68;
constexpr int VP = 72;

constexpr int Q_OFF   = 0;                    // 32*68   = 2176 floats
constexpr int KV_OFF  = Q_OFF + MT * QP;      // 128*72  = 9216 floats (K or V tile; phase-2 scratch)
constexpr int RED_OFF = KV_OFF + NTILE * VP;  // 6144 floats (k-split reduce)
constexpr int MSK_OFF = RED_OFF + 6144;       // 1024 ints
constexpr int SMEM_FLOATS = MSK_OFF + Nc;     // 18560
constexpr size_t SMEM_BYTES = (size_t)SMEM_FLOATS * 4;   // 74,240 B -> 3 CTAs/SM

#define NEG_INF_F (-1e9f)

__device__ __forceinline__ void tf32_split(float x, uint32_t& h, uint32_t& l) {
    asm("cvt.rna.tf32.f32 %0, %1;" : "=r"(h) : "f"(x));
    float hf = __uint_as_float(h);
    float r  = x - hf;
    asm("cvt.rna.tf32.f32 %0, %1;" : "=r"(l) : "f"(r));
}

__device__ __forceinline__ void mma_tf32(float* c, const uint32_t* a, uint32_t b0, uint32_t b1) {
    asm volatile(
        "mma.sync.aligned.m16n8k8.row.col.f32.tf32.tf32.f32 "
        "{%0,%1,%2,%3}, {%4,%5,%6,%7}, {%8,%9}, {%0,%1,%2,%3};\n"
        : "+f"(c[0]), "+f"(c[1]), "+f"(c[2]), "+f"(c[3])
        : "r"(a[0]), "r"(a[1]), "r"(a[2]), "r"(a[3]), "r"(b0), "r"(b1));
}

__global__ __launch_bounds__(THREADS, 3)
void attn_tc_kernel(const float* __restrict__ q,
                    const float* __restrict__ k,
                    const float* __restrict__ v,
                    const int*   __restrict__ mask,
                    float* __restrict__ outp,   // may be null
                    float* __restrict__ pp)     // S scratch + p_attn output
{
    extern __shared__ float smem[];
    float* Qs  = smem + Q_OFF;     // [MT][QP] raw Q
    float* KV  = smem + KV_OFF;    // raw K tile [NTILE][KP] / V tile [NTILE][VP] / phase-2 scratch
    float* Red = smem + RED_OFF;   // cross-warp k-split partial sums
    int*   Msk = (int*)(smem + MSK_OFF);

    const int mtiles = Mc / MT;
    const int bh = blockIdx.x / mtiles;
    const int m0 = (blockIdx.x % mtiles) * MT;
    const int tid  = threadIdx.x;
    const int wid  = tid >> 5;       // 0..7
    const int lane = tid & 31;
    const int g = lane >> 2;         // 0..7
    const int t = lane & 3;          // 0..3

    const float scale = 1.0f / 32.0f;  // 1/sqrt(N=1024), faithful to the source bug

    float* Sbase = pp + ((size_t)bh * Mc + m0) * Nc;   // this CTA's 32 rows of p_attn

    // ---- stage Q (raw fp32, pitch QP) + mask ----
    {
        const float4* qg = (const float4*)(q + (size_t)(bh * Mc + m0) * Dc);
        #pragma unroll
        for (int i = 0; i < (MT * Dc / 4) / THREADS; i++) {
            int f4 = i * THREADS + tid;
            float4 val = qg[f4];
            int row = f4 >> 4;
            int c   = (f4 & 15) * 4;
            *(float4*)(Qs + row * QP + c) = val;
        }
    }
    #pragma unroll
    for (int i = 0; i < Nc / THREADS; i++)
        Msk[i * THREADS + tid] = mask[(size_t)bh * Nc + i * THREADS + tid];

    // =================== phase 1: S = mask(scale(Q K^T)) -> gmem ===============
    // warp = (kh, nbp): kh = k-half [kh*32,+32), nbp -> n-slice [nbp*32,+32)
    const int kh  = wid >> 2;
    const int nbp = wid & 3;

    for (int nt = 0; nt < Nc / NTILE; nt++) {
        __syncthreads();
        {   // stage raw K tile [NTILE][Dc] -> pitch KP
            const float4* kg = (const float4*)(k + (size_t)(bh * Nc + nt * NTILE) * Dc);
            #pragma unroll
            for (int i = 0; i < (NTILE * Dc / 4) / THREADS; i++) {
                int f4 = i * THREADS + tid;
                float4 val = kg[f4];
                int row = f4 >> 4;
                int c   = (f4 & 15) * 4;
                *(float4*)(KV + row * KP + c) = val;
            }
        }
        __syncthreads();

        float acc[4][2][4] = {};   // [nb][mi][frag]
        #pragma unroll
        for (int kc = 0; kc < 4; kc++) {
            const int k0 = kh * 32 + kc * 8;
            uint32_t ah[2][4], al[2][4];
            #pragma unroll
            for (int mi = 0; mi < 2; mi++) {
                const int base = (mi * 16 + g) * QP + k0;
                tf32_split(Qs[base + t],              ah[mi][0], al[mi][0]);
                tf32_split(Qs[base + 8 * QP + t],     ah[mi][1], al[mi][1]);
                tf32_split(Qs[base + t + 4],          ah[mi][2], al[mi][2]);
                tf32_split(Qs[base + 8 * QP + t + 4], ah[mi][3], al[mi][3]);
            }
            #pragma unroll
            for (int nb = 0; nb < 4; nb++) {
                const int base = (nbp * 32 + nb * 8 + g) * KP + k0;
                uint32_t bh0, bl0, bh1, bl1;
                tf32_split(KV[base + t],     bh0, bl0);
                tf32_split(KV[base + t + 4], bh1, bl1);
                #pragma unroll
                for (int mi = 0; mi < 2; mi++) {
                    mma_tf32(acc[nb][mi], ah[mi], bh0, bh1);  // hi*hi
                    mma_tf32(acc[nb][mi], al[mi], bh0, bh1);  // lo*hi
                    mma_tf32(acc[nb][mi], ah[mi], bl0, bl1);  // hi*lo
                }
            }
        }
        // k-half reduce: kh=1 publishes, kh=0 adds + masks + scales + stores S->gmem
        if (kh == 1) {
            #pragma unroll
            for (int nb = 0; nb < 4; nb++)
                #pragma unroll
                for (int mi = 0; mi < 2; mi++)
                    *(float4*)(Red + ((nbp * 4 + nb) * 2 + mi) * 128 + lane * 4) =
                        make_float4(acc[nb][mi][0], acc[nb][mi][1], acc[nb][mi][2], acc[nb][mi][3]);
        }
        __syncthreads();
        if (kh == 0) {
            #pragma unroll
            for (int nb = 0; nb < 4; nb++)
                #pragma unroll
                for (int mi = 0; mi < 2; mi++) {
                    float4 r = *(float4*)(Red + ((nbp * 4 + nb) * 2 + mi) * 128 + lane * 4);
                    const int m = mi * 16 + g;
                    const int n = nt * NTILE + nbp * 32 + nb * 8 + 2 * t;
                    const bool m0ok = Msk[n] != 0;
                    const bool m1ok = Msk[n + 1] != 0;
                    float s00 = m0ok ? (acc[nb][mi][0] + r.x) * scale : NEG_INF_F;
                    float s01 = m1ok ? (acc[nb][mi][1] + r.y) * scale : NEG_INF_F;
                    float s10 = m0ok ? (acc[nb][mi][2] + r.z) * scale : NEG_INF_F;
                    float s11 = m1ok ? (acc[nb][mi][3] + r.w) * scale : NEG_INF_F;
                    *(float2*)(Sbase + (size_t)m * Nc + n)       = make_float2(s00, s01);
                    *(float2*)(Sbase + (size_t)(m + 8) * Nc + n) = make_float2(s10, s11);
                }
        }
    }
    __syncthreads();

    // =================== phase 2: softmax over gmem rows (L2-hot) ==============
    // warp wid owns rows wid*4 .. wid*4+3; e-values staged in KV scratch
    {
        float* KVs = KV + wid * 1024;
        #pragma unroll
        for (int rr = 0; rr < 4; rr++) {
            const int m = wid * 4 + rr;
            float* prow = Sbase + (size_t)m * Nc;
            float mx = NEG_INF_F;
            #pragma unroll 8
            for (int i = 0; i < 32; i++) {
                float vv = prow[i * 32 + lane];
                KVs[i * 32 + lane] = vv;
                mx = fmaxf(mx, vv);
            }
            #pragma unroll
            for (int o = 16; o; o >>= 1) mx = fmaxf(mx, __shfl_xor_sync(0xffffffffu, mx, o));
            float sum = 0.0f;
            #pragma unroll 8
            for (int i = 0; i < 32; i++) {
                float e = __expf(KVs[i * 32 + lane] - mx);
                KVs[i * 32 + lane] = e;
                sum += e;
            }
            #pragma unroll
            for (int o = 16; o; o >>= 1) sum += __shfl_xor_sync(0xffffffffu, sum, o);
            const float inv = 1.0f / sum;
            #pragma unroll 8
            for (int i = 0; i < 32; i++)
                prow[i * 32 + lane] = KVs[i * 32 + lane] * inv;   // final p_attn, coalesced
        }
    }

    // =================== phase 3: out = P V (tensor, 3xTF32, k-quarter split) ==
    // warp = (mi3, kq): mi3 = m-half (16 rows), kq = k-quarter of each tile; full d=64
    const int mi3 = wid & 1;
    const int kq  = wid >> 1;

    float oacc[8][4] = {};   // [db][frag], d = db*8 + ...
    for (int nt = 0; nt < Nc / NTILE; nt++) {
        __syncthreads();   // phase-2 scratch / previous V reads done
        {   // stage raw V tile [NTILE][Dc] -> pitch VP
            const float4* vg = (const float4*)(v + (size_t)(bh * Nc + nt * NTILE) * Dc);
            #pragma unroll
            for (int i = 0; i < (NTILE * Dc / 4) / THREADS; i++) {
                int f4 = i * THREADS + tid;
                float4 val = vg[f4];
                int row = f4 >> 4;
                int c   = (f4 & 15) * 4;
                *(float4*)(KV + row * VP + c) = val;
            }
        }
        __syncthreads();

        #pragma unroll
        for (int kc = 0; kc < 4; kc++) {
            const int kk = kq * 32 + kc * 8;   // local row in tile
            // A fragment: p from gmem (L2-hot, written by this CTA in phase 2)
            const float* pb = Sbase + (size_t)(mi3 * 16 + g) * Nc + nt * NTILE + kk;
            uint32_t pah[4], pal[4];
            tf32_split(pb[t],              pah[0], pal[0]);
            tf32_split(pb[8 * Nc + t],     pah[1], pal[1]);
            tf32_split(pb[t + 4],          pah[2], pal[2]);
            tf32_split(pb[8 * Nc + t + 4], pah[3], pal[3]);
            #pragma unroll
            for (int db = 0; db < 8; db++) {
                const int base = (kk + t) * VP + db * 8 + g;
                uint32_t bh0, bl0, bh1, bl1;
                tf32_split(KV[base],          bh0, bl0);
                tf32_split(KV[base + 4 * VP], bh1, bl1);
                mma_tf32(oacc[db], pah, bh0, bh1);
                mma_tf32(oacc[db], pal, bh0, bh1);
                mma_tf32(oacc[db], pah, bl0, bl1);
            }
        }
    }
    __syncthreads();
    // k-quarter reduce: kq 1..3 publish, kq 0 sums and stores out
    if (kq != 0) {
        #pragma unroll
        for (int db = 0; db < 8; db++)
            *(float4*)(Red + ((mi3 * 3 + (kq - 1)) * 8 + db) * 128 + lane * 4) =
                make_float4(oacc[db][0], oacc[db][1], oacc[db][2], oacc[db][3]);
    }
    __syncthreads();
    if (kq == 0 && outp) {
        #pragma unroll
        for (int db = 0; db < 8; db++) {
            float4 r1 = *(float4*)(Red + ((mi3 * 3 + 0) * 8 + db) * 128 + lane * 4);
            float4 r2 = *(float4*)(Red + ((mi3 * 3 + 1) * 8 + db) * 128 + lane * 4);
            float4 r3 = *(float4*)(Red + ((mi3 * 3 + 2) * 8 + db) * 128 + lane * 4);
            const int m = mi3 * 16 + g;
            float* ob = outp + ((size_t)bh * Mc + m0 + m) * Dc + db * 8 + 2 * t;
            *(float2*)ob = make_float2(oacc[db][0] + r1.x + r2.x + r3.x,
                                       oacc[db][1] + r1.y + r2.y + r3.y);
            *(float2*)(ob + 8 * Dc) = make_float2(oacc[db][2] + r1.z + r2.z + r3.z,
                                                  oacc[db][3] + r1.w + r2.w + r3.w);
        }
    }
}

extern "C" void kernel_launch(void* const* d_in, const int* in_sizes, int n_in,
                              void* d_out, int out_size)
{
    const float* q    = (const float*)d_in[0];
    const float* k    = (const float*)d_in[1];
    const float* v    = (const float*)d_in[2];
    const int*   mask = (const int*)d_in[3];

    float* outp = nullptr;
    float* pp   = nullptr;
    long long osz = (long long)out_size;
    if (osz >= OUT_ELEMS + P_ELEMS) {            // (out, p_attn) concatenated
        outp = (float*)d_out;
        pp   = (float*)d_out + OUT_ELEMS;
    } else {                                     // p_attn only
        pp   = (float*)d_out;
    }

    cudaFuncSetAttribute(attn_tc_kernel,
                         cudaFuncAttributeMaxDynamicSharedMemorySize,
                         (int)SMEM_BYTES);

    dim3 grid(BHc * (Mc / MT));   // 4096 CTAs; consecutive CTAs share (b,h) -> K/V L2 reuse
    attn_tc_kernel<<<grid, THREADS, SMEM_BYTES>>>(q, k, v, mask, outp, pp);
}